// round 1
// baseline (speedup 1.0000x reference)
#include <cuda_runtime.h>
#include <math.h>

#define BATCH  2
#define SEQ    2048
#define DM     1024
#define NHEADS 16
#define HD     64
#define MTOT   (BATCH * SEQ)   // 4096

// ---------------- scratch (static device globals; no runtime alloc) --------
__device__ float g_q[MTOT * DM];
__device__ float g_k[MTOT * DM];
__device__ float g_v[MTOT * DM];
__device__ float g_ctx[MTOT * DM];

// ---------------- generic fp32 GEMM: C[M,1024] = A[M,1024] @ B[1024,1024] --
// BM=128, BN=64, BK=16, 256 threads, 8x4 outputs per thread.
#define GBM 128
#define GBN 64
#define GBK 16

__global__ __launch_bounds__(256) void gemm_kernel(
    const float* __restrict__ Aparam, const float* __restrict__ B,
    const float* __restrict__ bias, float* __restrict__ Cparam, int mode)
{
    // mode 0/1/2: A = Aparam (x), C = g_q/g_k/g_v, no bias
    // mode 3:     A = g_ctx,      C = Cparam (d_out), add bias
    __shared__ float As[GBK][GBM + 4];   // transposed A tile, padded pitch 132
    __shared__ float Bs[GBK][GBN];

    const float* A = (mode == 3) ? g_ctx : Aparam;
    float* C = (mode == 0) ? g_q : (mode == 1) ? g_k : (mode == 2) ? g_v : Cparam;

    const int tid = threadIdx.x;
    const int tx = tid & 15;        // 16 col-groups of 4  -> 64 cols
    const int ty = tid >> 4;        // 16 row-groups of 8  -> 128 rows
    const int m0 = blockIdx.y * GBM;
    const int n0 = blockIdx.x * GBN;

    float acc[8][4];
#pragma unroll
    for (int i = 0; i < 8; i++)
#pragma unroll
        for (int j = 0; j < 4; j++) acc[i][j] = 0.f;

    for (int kt = 0; kt < DM; kt += GBK) {
        // load A tile (128x16), store transposed
#pragma unroll
        for (int i = 0; i < 2; i++) {
            int idx = tid + i * 256;            // 0..511
            int row = idx >> 2;                 // 0..127
            int kc  = (idx & 3) << 2;           // 0,4,8,12
            float4 va = *(const float4*)&A[(size_t)(m0 + row) * DM + kt + kc];
            As[kc + 0][row] = va.x;
            As[kc + 1][row] = va.y;
            As[kc + 2][row] = va.z;
            As[kc + 3][row] = va.w;
        }
        // load B tile (16x64)
        {
            int kk = tid >> 4;                  // 0..15
            int c  = (tid & 15) << 2;           // 0..60
            *(float4*)&Bs[kk][c] = *(const float4*)&B[(size_t)(kt + kk) * DM + n0 + c];
        }
        __syncthreads();

#pragma unroll
        for (int k = 0; k < GBK; k++) {
            float4 a0 = *(const float4*)&As[k][ty * 8];
            float4 a1 = *(const float4*)&As[k][ty * 8 + 4];
            float4 b0 = *(const float4*)&Bs[k][tx * 4];
            float a[8] = {a0.x, a0.y, a0.z, a0.w, a1.x, a1.y, a1.z, a1.w};
            float bb[4] = {b0.x, b0.y, b0.z, b0.w};
#pragma unroll
            for (int i = 0; i < 8; i++)
#pragma unroll
                for (int j = 0; j < 4; j++)
                    acc[i][j] += a[i] * bb[j];
        }
        __syncthreads();
    }

    float4 bv = make_float4(0.f, 0.f, 0.f, 0.f);
    if (mode == 3) bv = *(const float4*)&bias[n0 + tx * 4];
#pragma unroll
    for (int i = 0; i < 8; i++) {
        float4 v = make_float4(acc[i][0] + bv.x, acc[i][1] + bv.y,
                               acc[i][2] + bv.z, acc[i][3] + bv.w);
        *(float4*)&C[(size_t)(m0 + ty * 8 + i) * DM + n0 + tx * 4] = v;
    }
}

// ---------------- flash attention, fp32, causal ----------------------------
// Block = (qtile=64, head, batch). 256 threads; thread (tx,ty) owns a 4x4
// patch of the 64x64 S tile / O tile. Online softmax with shfl row-reduce
// across the 16 lanes sharing a row group (lanes stay inside a half-warp).
#define AT     64
#define APITCH 68
#define ASMEM  (4 * AT * APITCH * sizeof(float))   // Qs, Ks, Vs, Ss = 69632 B

__global__ __launch_bounds__(256) void attn_kernel()
{
    extern __shared__ float smem[];
    float* Qs = smem;
    float* Ks = Qs + AT * APITCH;
    float* Vs = Ks + AT * APITCH;
    float* Ss = Vs + AT * APITCH;

    const int qt  = blockIdx.x;          // 0..31
    const int h   = blockIdx.y;          // 0..15
    const int b   = blockIdx.z;          // 0..1
    const int tid = threadIdx.x;
    const int tx  = tid & 15;
    const int ty  = tid >> 4;

    const int q0 = qt * AT;
    const size_t headoff = (size_t)b * SEQ * DM + (size_t)h * HD;

    // load Q tile (64 rows x 64 dims)
#pragma unroll
    for (int i = 0; i < 4; i++) {
        int idx = tid + i * 256;
        int row = idx >> 4;
        int c   = (idx & 15) << 2;
        *(float4*)&Qs[row * APITCH + c] =
            *(const float4*)&g_q[headoff + (size_t)(q0 + row) * DM + c];
    }

    float m_i[4], l_i[4], o[4][4];
#pragma unroll
    for (int i = 0; i < 4; i++) {
        m_i[i] = -1e30f;
        l_i[i] = 0.f;
#pragma unroll
        for (int j = 0; j < 4; j++) o[i][j] = 0.f;
    }

    __syncthreads();

    for (int jt = 0; jt <= qt; jt++) {
        const int k0 = jt * AT;
        // load K, V tiles
#pragma unroll
        for (int i = 0; i < 4; i++) {
            int idx = tid + i * 256;
            int row = idx >> 4;
            int c   = (idx & 15) << 2;
            *(float4*)&Ks[row * APITCH + c] =
                *(const float4*)&g_k[headoff + (size_t)(k0 + row) * DM + c];
            *(float4*)&Vs[row * APITCH + c] =
                *(const float4*)&g_v[headoff + (size_t)(k0 + row) * DM + c];
        }
        __syncthreads();

        // S = Q @ K^T  (4x4 patch per thread)
        float s[4][4];
#pragma unroll
        for (int i = 0; i < 4; i++)
#pragma unroll
            for (int j = 0; j < 4; j++) s[i][j] = 0.f;

#pragma unroll
        for (int k4 = 0; k4 < HD; k4 += 4) {
            float4 qv[4], kv[4];
#pragma unroll
            for (int i = 0; i < 4; i++)
                qv[i] = *(const float4*)&Qs[(ty * 4 + i) * APITCH + k4];
#pragma unroll
            for (int j = 0; j < 4; j++)
                kv[j] = *(const float4*)&Ks[(tx * 4 + j) * APITCH + k4];
#pragma unroll
            for (int i = 0; i < 4; i++)
#pragma unroll
                for (int j = 0; j < 4; j++)
                    s[i][j] += qv[i].x * kv[j].x + qv[i].y * kv[j].y +
                               qv[i].z * kv[j].z + qv[i].w * kv[j].w;
        }

        // causal mask (reference: where(mask, s, -1e9) then /sqrt(64))
        const bool diag = (jt == qt);
#pragma unroll
        for (int i = 0; i < 4; i++) {
            int grow = q0 + ty * 4 + i;
#pragma unroll
            for (int j = 0; j < 4; j++) {
                int gcol = k0 + tx * 4 + j;
                float sv = s[i][j];
                if (diag && gcol > grow) sv = -1e9f;
                s[i][j] = sv * 0.125f;
            }
        }

        // online softmax per row (reduce across the 16 lanes of this ty group)
#pragma unroll
        for (int i = 0; i < 4; i++) {
            float rm = fmaxf(fmaxf(s[i][0], s[i][1]), fmaxf(s[i][2], s[i][3]));
#pragma unroll
            for (int off = 1; off < 16; off <<= 1)
                rm = fmaxf(rm, __shfl_xor_sync(0xffffffffu, rm, off));
            float m_new = fmaxf(m_i[i], rm);
            float alpha = __expf(m_i[i] - m_new);
            float rs = 0.f;
#pragma unroll
            for (int j = 0; j < 4; j++) {
                s[i][j] = __expf(s[i][j] - m_new);
                rs += s[i][j];
            }
#pragma unroll
            for (int off = 1; off < 16; off <<= 1)
                rs += __shfl_xor_sync(0xffffffffu, rs, off);
            l_i[i] = l_i[i] * alpha + rs;
            m_i[i] = m_new;
#pragma unroll
            for (int j = 0; j < 4; j++) o[i][j] *= alpha;
            *(float4*)&Ss[(ty * 4 + i) * APITCH + tx * 4] =
                make_float4(s[i][0], s[i][1], s[i][2], s[i][3]);
        }
        __syncthreads();

        // O += P @ V
#pragma unroll
        for (int k4 = 0; k4 < AT; k4 += 4) {
            float4 pv[4], vv[4];
#pragma unroll
            for (int i = 0; i < 4; i++)
                pv[i] = *(const float4*)&Ss[(ty * 4 + i) * APITCH + k4];
#pragma unroll
            for (int kk = 0; kk < 4; kk++)
                vv[kk] = *(const float4*)&Vs[(k4 + kk) * APITCH + tx * 4];
#pragma unroll
            for (int i = 0; i < 4; i++) {
                o[i][0] += pv[i].x * vv[0].x + pv[i].y * vv[1].x + pv[i].z * vv[2].x + pv[i].w * vv[3].x;
                o[i][1] += pv[i].x * vv[0].y + pv[i].y * vv[1].y + pv[i].z * vv[2].y + pv[i].w * vv[3].y;
                o[i][2] += pv[i].x * vv[0].z + pv[i].y * vv[1].z + pv[i].z * vv[2].z + pv[i].w * vv[3].z;
                o[i][3] += pv[i].x * vv[0].w + pv[i].y * vv[1].w + pv[i].z * vv[2].w + pv[i].w * vv[3].w;
            }
        }
        __syncthreads();
    }

    // normalize and store ctx tile
#pragma unroll
    for (int i = 0; i < 4; i++) {
        float inv = 1.f / l_i[i];
        float4 v = make_float4(o[i][0] * inv, o[i][1] * inv,
                               o[i][2] * inv, o[i][3] * inv);
        *(float4*)&g_ctx[headoff + (size_t)(q0 + ty * 4 + i) * DM + tx * 4] = v;
    }
}

// ---------------- launch ---------------------------------------------------
extern "C" void kernel_launch(void* const* d_in, const int* in_sizes, int n_in,
                              void* d_out, int out_size)
{
    const float* x  = (const float*)d_in[0];
    const float* Wq = (const float*)d_in[1];
    const float* Wk = (const float*)d_in[2];
    const float* Wv = (const float*)d_in[3];
    const float* Wo = (const float*)d_in[4];
    const float* bo = (const float*)d_in[5];
    float* out = (float*)d_out;

    dim3 ggrid(DM / GBN, MTOT / GBM);   // (16, 32) = 512 blocks

    gemm_kernel<<<ggrid, 256>>>(x, Wq, nullptr, nullptr, 0);
    gemm_kernel<<<ggrid, 256>>>(x, Wk, nullptr, nullptr, 1);
    gemm_kernel<<<ggrid, 256>>>(x, Wv, nullptr, nullptr, 2);

    cudaFuncSetAttribute(attn_kernel,
                         cudaFuncAttributeMaxDynamicSharedMemorySize, (int)ASMEM);
    dim3 agrid(SEQ / AT, NHEADS, BATCH);  // (32, 16, 2)
    attn_kernel<<<agrid, 256, ASMEM>>>();

    gemm_kernel<<<ggrid, 256>>>(nullptr, Wo, bo, out, 3);
}

// round 4
// speedup vs baseline: 3.6789x; 3.6789x over previous
#include <cuda_runtime.h>
#include <math.h>
#include <stdint.h>

#define BATCH  2
#define SEQ    2048
#define DM     1024
#define NHEADS 16
#define HD     64
#define MTOT   (BATCH * SEQ)   // 4096

// ---------------- scratch (static device globals; no runtime alloc) --------
__device__ float g_q[MTOT * DM];
__device__ float g_k[MTOT * DM];
__device__ float g_v[MTOT * DM];
__device__ float g_ctx[MTOT * DM];
__device__ float g_wt[4 * DM * DM];   // transposed weights, K-major [N][K]

// ============================ helpers ======================================
__device__ __forceinline__ float tf32r(float x) {
    uint32_t r;
    asm("cvt.rna.tf32.f32 %0, %1;" : "=r"(r) : "f"(x));   // dst must be .b32
    return __uint_as_float(r);
}
__device__ __forceinline__ uint32_t fu(float x) { return __float_as_uint(x); }

// D += A(16x8, row) * B(8x8, col), tf32 inputs, fp32 accum
__device__ __forceinline__ void mma8(float d[4], uint32_t a0, uint32_t a1,
                                     uint32_t a2, uint32_t a3,
                                     uint32_t b0, uint32_t b1) {
    asm volatile(
        "mma.sync.aligned.m16n8k8.row.col.f32.tf32.tf32.f32 "
        "{%0,%1,%2,%3}, {%4,%5,%6,%7}, {%8,%9}, {%0,%1,%2,%3};"
        : "+f"(d[0]), "+f"(d[1]), "+f"(d[2]), "+f"(d[3])
        : "r"(a0), "r"(a1), "r"(a2), "r"(a3), "r"(b0), "r"(b1));
}

// ================= weight transpose: Wt[n][k] = W[k][n] ====================
__global__ __launch_bounds__(256) void transpose4(
    const float* __restrict__ W0, const float* __restrict__ W1,
    const float* __restrict__ W2, const float* __restrict__ W3)
{
    __shared__ float t[32][33];
    const float* src = (blockIdx.z == 0) ? W0 : (blockIdx.z == 1) ? W1
                     : (blockIdx.z == 2) ? W2 : W3;
    float* dst = g_wt + (size_t)blockIdx.z * DM * DM;
    int bk = blockIdx.y * 32, bn = blockIdx.x * 32;
    int tx = threadIdx.x & 31, ty = threadIdx.x >> 5;
#pragma unroll
    for (int i = 0; i < 4; i++)
        t[ty + 8 * i][tx] = src[(size_t)(bk + ty + 8 * i) * DM + bn + tx];
    __syncthreads();
#pragma unroll
    for (int i = 0; i < 4; i++)
        dst[(size_t)(bn + ty + 8 * i) * DM + bk + tx] = t[tx][ty + 8 * i];
}

// ============== tf32 mma.sync GEMM: C[M,1024] = A @ Bt^T (+bias) ===========
// BM=BN=128, BK=32; 256 threads = 8 warps (2 x 4); warp tile 64x32.
// smem pitch 36: fragment addr = row*36 + k -> bank (4*g + t), conflict-free.
#define GBM 128
#define GBN 128
#define GBK 32

__global__ __launch_bounds__(256) void gemm_mma(
    const float* __restrict__ A, const float* __restrict__ Bt,
    float* __restrict__ C, const float* __restrict__ bias)
{
    __shared__ float As[GBM][36];
    __shared__ float Bs[GBN][36];

    const int tid = threadIdx.x;
    const int warp = tid >> 5, lane = tid & 31;
    const int g = lane >> 2, t = lane & 3;
    const int wm = (warp >> 2) * 64;     // 0 / 64
    const int wn = (warp & 3) * 32;      // 0..96
    const int m0 = blockIdx.y * GBM;
    const int n0 = blockIdx.x * GBN;

    float acc[4][4][4] = {};

    float4 ra[4], rb[4];
#pragma unroll
    for (int it = 0; it < 4; it++) {
        int idx = tid + it * 256;
        int row = idx >> 3, c4 = (idx & 7) << 2;
        ra[it] = *(const float4*)&A[(size_t)(m0 + row) * DM + c4];
        rb[it] = *(const float4*)&Bt[(size_t)(n0 + row) * DM + c4];
    }

    for (int kt = 0; kt < DM; kt += GBK) {
#pragma unroll
        for (int it = 0; it < 4; it++) {
            int idx = tid + it * 256;
            int row = idx >> 3, c4 = (idx & 7) << 2;
            float4 va = ra[it], vb = rb[it];
            As[row][c4 + 0] = tf32r(va.x); As[row][c4 + 1] = tf32r(va.y);
            As[row][c4 + 2] = tf32r(va.z); As[row][c4 + 3] = tf32r(va.w);
            Bs[row][c4 + 0] = tf32r(vb.x); Bs[row][c4 + 1] = tf32r(vb.y);
            Bs[row][c4 + 2] = tf32r(vb.z); Bs[row][c4 + 3] = tf32r(vb.w);
        }
        __syncthreads();
        if (kt + GBK < DM) {
#pragma unroll
            for (int it = 0; it < 4; it++) {
                int idx = tid + it * 256;
                int row = idx >> 3, c4 = (idx & 7) << 2;
                ra[it] = *(const float4*)&A[(size_t)(m0 + row) * DM + kt + GBK + c4];
                rb[it] = *(const float4*)&Bt[(size_t)(n0 + row) * DM + kt + GBK + c4];
            }
        }
#pragma unroll
        for (int ks = 0; ks < 4; ks++) {
            const int k8 = ks * 8;
            uint32_t af[4][4];
#pragma unroll
            for (int mt = 0; mt < 4; mt++) {
                int ar = wm + mt * 16;
                af[mt][0] = fu(As[ar + g][k8 + t]);
                af[mt][1] = fu(As[ar + g + 8][k8 + t]);
                af[mt][2] = fu(As[ar + g][k8 + t + 4]);
                af[mt][3] = fu(As[ar + g + 8][k8 + t + 4]);
            }
#pragma unroll
            for (int nt = 0; nt < 4; nt++) {
                int bc = wn + nt * 8;
                uint32_t b0 = fu(Bs[bc + g][k8 + t]);
                uint32_t b1 = fu(Bs[bc + g][k8 + t + 4]);
#pragma unroll
                for (int mt = 0; mt < 4; mt++)
                    mma8(acc[mt][nt], af[mt][0], af[mt][1], af[mt][2], af[mt][3],
                         b0, b1);
            }
        }
        __syncthreads();
    }

#pragma unroll
    for (int mt = 0; mt < 4; mt++) {
        int r0 = m0 + wm + mt * 16 + g;
#pragma unroll
        for (int nt = 0; nt < 4; nt++) {
            int col = n0 + wn + nt * 8 + 2 * t;
            float bv0 = 0.f, bv1 = 0.f;
            if (bias) { bv0 = bias[col]; bv1 = bias[col + 1]; }
            *(float2*)&C[(size_t)r0 * DM + col] =
                make_float2(acc[mt][nt][0] + bv0, acc[mt][nt][1] + bv1);
            *(float2*)&C[(size_t)(r0 + 8) * DM + col] =
                make_float2(acc[mt][nt][2] + bv0, acc[mt][nt][3] + bv1);
        }
    }
}

// ============== flash attention with tf32 mma.sync, causal =================
// Block: 64 queries x head x batch; 4 warps, warp owns 16 query rows.
#define QP 68   // pitch for Qs/Ks/Ps
#define VP 72   // pitch for Vs
#define ASMEM ((64 * (QP + QP + VP + QP)) * sizeof(float))   // 70656 B

__global__ __launch_bounds__(128) void attn_mma()
{
    extern __shared__ float sm[];
    float* Qs = sm;                  // [64][68]
    float* Ks = Qs + 64 * QP;        // [64][68]
    float* Vs = Ks + 64 * QP;        // [64][72]
    float* Ps = Vs + 64 * VP;        // [64][68]

    const int qt = blockIdx.x, h = blockIdx.y, b = blockIdx.z;
    const int tid = threadIdx.x;
    const int warp = tid >> 5, lane = tid & 31;
    const int g = lane >> 2, t = lane & 3;
    const int q0 = qt * 64;
    const int qrow = warp * 16;
    const size_t headoff = (size_t)b * SEQ * DM + (size_t)h * HD;

#pragma unroll
    for (int it = 0; it < 8; it++) {
        int idx = tid + it * 128;
        int row = idx >> 4, c = (idx & 15) << 2;
        float4 v = *(const float4*)&g_q[headoff + (size_t)(q0 + row) * DM + c];
        v.x = tf32r(v.x); v.y = tf32r(v.y); v.z = tf32r(v.z); v.w = tf32r(v.w);
        *(float4*)&Qs[row * QP + c] = v;
    }

    float m0r = -1e30f, m1r = -1e30f, l0 = 0.f, l1 = 0.f;
    float oacc[8][4] = {};
    __syncthreads();

    for (int jt = 0; jt <= qt; jt++) {
        const int k0 = jt * 64;
#pragma unroll
        for (int it = 0; it < 8; it++) {
            int idx = tid + it * 128;
            int row = idx >> 4, c = (idx & 15) << 2;
            float4 kv = *(const float4*)&g_k[headoff + (size_t)(k0 + row) * DM + c];
            kv.x = tf32r(kv.x); kv.y = tf32r(kv.y);
            kv.z = tf32r(kv.z); kv.w = tf32r(kv.w);
            *(float4*)&Ks[row * QP + c] = kv;
            float4 vv = *(const float4*)&g_v[headoff + (size_t)(k0 + row) * DM + c];
            vv.x = tf32r(vv.x); vv.y = tf32r(vv.y);
            vv.z = tf32r(vv.z); vv.w = tf32r(vv.w);
            *(float4*)&Vs[row * VP + c] = vv;
        }
        __syncthreads();

        // S = Q @ K^T  (warp: 16 x 64)
        float sacc[8][4] = {};
#pragma unroll
        for (int ks = 0; ks < 8; ks++) {
            const int k8 = ks * 8;
            uint32_t a0 = fu(Qs[(qrow + g) * QP + k8 + t]);
            uint32_t a1 = fu(Qs[(qrow + g + 8) * QP + k8 + t]);
            uint32_t a2 = fu(Qs[(qrow + g) * QP + k8 + t + 4]);
            uint32_t a3 = fu(Qs[(qrow + g + 8) * QP + k8 + t + 4]);
#pragma unroll
            for (int nt = 0; nt < 8; nt++) {
                uint32_t b0 = fu(Ks[(nt * 8 + g) * QP + k8 + t]);
                uint32_t b1 = fu(Ks[(nt * 8 + g) * QP + k8 + t + 4]);
                mma8(sacc[nt], a0, a1, a2, a3, b0, b1);
            }
        }

        const int r0 = q0 + qrow + g, r1 = r0 + 8;
        if (jt == qt) {   // causal mask on diagonal tile (pre-scale, like ref)
#pragma unroll
            for (int nt = 0; nt < 8; nt++) {
                int c0 = k0 + nt * 8 + 2 * t, c1 = c0 + 1;
                if (c0 > r0) sacc[nt][0] = -1e9f;
                if (c1 > r0) sacc[nt][1] = -1e9f;
                if (c0 > r1) sacc[nt][2] = -1e9f;
                if (c1 > r1) sacc[nt][3] = -1e9f;
            }
        }
#pragma unroll
        for (int nt = 0; nt < 8; nt++)
#pragma unroll
            for (int j = 0; j < 4; j++) sacc[nt][j] *= 0.125f;

        // online softmax; rows r0 (regs 0,1) and r1 (regs 2,3)
        float rm0 = -1e30f, rm1 = -1e30f;
#pragma unroll
        for (int nt = 0; nt < 8; nt++) {
            rm0 = fmaxf(rm0, fmaxf(sacc[nt][0], sacc[nt][1]));
            rm1 = fmaxf(rm1, fmaxf(sacc[nt][2], sacc[nt][3]));
        }
#pragma unroll
        for (int off = 1; off < 4; off <<= 1) {
            rm0 = fmaxf(rm0, __shfl_xor_sync(0xffffffffu, rm0, off));
            rm1 = fmaxf(rm1, __shfl_xor_sync(0xffffffffu, rm1, off));
        }
        float mn0 = fmaxf(m0r, rm0), mn1 = fmaxf(m1r, rm1);
        float al0 = __expf(m0r - mn0), al1 = __expf(m1r - mn1);
        float rs0 = 0.f, rs1 = 0.f;
#pragma unroll
        for (int nt = 0; nt < 8; nt++) {
            sacc[nt][0] = __expf(sacc[nt][0] - mn0);
            sacc[nt][1] = __expf(sacc[nt][1] - mn0);
            sacc[nt][2] = __expf(sacc[nt][2] - mn1);
            sacc[nt][3] = __expf(sacc[nt][3] - mn1);
            rs0 += sacc[nt][0] + sacc[nt][1];
            rs1 += sacc[nt][2] + sacc[nt][3];
        }
#pragma unroll
        for (int off = 1; off < 4; off <<= 1) {
            rs0 += __shfl_xor_sync(0xffffffffu, rs0, off);
            rs1 += __shfl_xor_sync(0xffffffffu, rs1, off);
        }
        l0 = l0 * al0 + rs0;
        l1 = l1 * al1 + rs1;
        m0r = mn0; m1r = mn1;
#pragma unroll
        for (int nt = 0; nt < 8; nt++) {
            oacc[nt][0] *= al0; oacc[nt][1] *= al0;
            oacc[nt][2] *= al1; oacc[nt][3] *= al1;
        }

        // P -> smem (C-frag layout -> A-frag reload); warp-private rows
#pragma unroll
        for (int nt = 0; nt < 8; nt++) {
            *(float2*)&Ps[(qrow + g) * QP + nt * 8 + 2 * t] =
                make_float2(tf32r(sacc[nt][0]), tf32r(sacc[nt][1]));
            *(float2*)&Ps[(qrow + g + 8) * QP + nt * 8 + 2 * t] =
                make_float2(tf32r(sacc[nt][2]), tf32r(sacc[nt][3]));
        }
        __syncwarp();

        // O += P @ V
#pragma unroll
        for (int ks = 0; ks < 8; ks++) {
            const int k8 = ks * 8;
            uint32_t a0 = fu(Ps[(qrow + g) * QP + k8 + t]);
            uint32_t a1 = fu(Ps[(qrow + g + 8) * QP + k8 + t]);
            uint32_t a2 = fu(Ps[(qrow + g) * QP + k8 + t + 4]);
            uint32_t a3 = fu(Ps[(qrow + g + 8) * QP + k8 + t + 4]);
#pragma unroll
            for (int nt = 0; nt < 8; nt++) {
                uint32_t b0 = fu(Vs[(k8 + t) * VP + nt * 8 + g]);
                uint32_t b1 = fu(Vs[(k8 + t + 4) * VP + nt * 8 + g]);
                mma8(oacc[nt], a0, a1, a2, a3, b0, b1);
            }
        }
        __syncthreads();
    }

    const float inv0 = 1.f / l0, inv1 = 1.f / l1;
    const int r0 = q0 + qrow + g, r1 = r0 + 8;
#pragma unroll
    for (int nt = 0; nt < 8; nt++) {
        int c = nt * 8 + 2 * t;
        *(float2*)&g_ctx[headoff + (size_t)r0 * DM + c] =
            make_float2(oacc[nt][0] * inv0, oacc[nt][1] * inv0);
        *(float2*)&g_ctx[headoff + (size_t)r1 * DM + c] =
            make_float2(oacc[nt][2] * inv1, oacc[nt][3] * inv1);
    }
}

// ---------------- launch ---------------------------------------------------
extern "C" void kernel_launch(void* const* d_in, const int* in_sizes, int n_in,
                              void* d_out, int out_size)
{
    const float* x  = (const float*)d_in[0];
    const float* Wq = (const float*)d_in[1];
    const float* Wk = (const float*)d_in[2];
    const float* Wv = (const float*)d_in[3];
    const float* Wo = (const float*)d_in[4];
    const float* bo = (const float*)d_in[5];
    float* out = (float*)d_out;

    float *gq, *gk, *gv, *gctx, *gwt;
    cudaGetSymbolAddress((void**)&gq, g_q);
    cudaGetSymbolAddress((void**)&gk, g_k);
    cudaGetSymbolAddress((void**)&gv, g_v);
    cudaGetSymbolAddress((void**)&gctx, g_ctx);
    cudaGetSymbolAddress((void**)&gwt, g_wt);

    transpose4<<<dim3(32, 32, 4), 256>>>(Wq, Wk, Wv, Wo);

    dim3 ggrid(DM / GBN, MTOT / GBM);   // (8, 32)
    gemm_mma<<<ggrid, 256>>>(x, gwt + 0 * DM * DM, gq, nullptr);
    gemm_mma<<<ggrid, 256>>>(x, gwt + 1 * DM * DM, gk, nullptr);
    gemm_mma<<<ggrid, 256>>>(x, gwt + 2 * DM * DM, gv, nullptr);

    cudaFuncSetAttribute(attn_mma,
                         cudaFuncAttributeMaxDynamicSharedMemorySize, (int)ASMEM);
    attn_mma<<<dim3(SEQ / 64, NHEADS, BATCH), 128, ASMEM>>>();

    gemm_mma<<<ggrid, 256>>>(gctx, gwt + 3 * DM * DM, out, bo);
}

// round 5
// speedup vs baseline: 4.2762x; 1.1624x over previous
#include <cuda_runtime.h>
#include <math.h>
#include <stdint.h>

#define BATCH  2
#define SEQ    2048
#define DM     1024
#define NHEADS 16
#define HD     64
#define MTOT   (BATCH * SEQ)   // 4096

// ---------------- scratch (static device globals; no runtime alloc) --------
__device__ float g_q[MTOT * DM];
__device__ float g_k[MTOT * DM];
__device__ float g_v[MTOT * DM];
__device__ float g_ctx[MTOT * DM];
__device__ float g_xr[MTOT * DM];     // x rounded to tf32
__device__ float g_wt[4 * DM * DM];   // transposed tf32-rounded weights [N][K]

// ============================ helpers ======================================
__device__ __forceinline__ float tf32r(float x) {
    uint32_t r;
    asm("cvt.rna.tf32.f32 %0, %1;" : "=r"(r) : "f"(x));
    return __uint_as_float(r);
}
__device__ __forceinline__ uint32_t fu(float x) { return __float_as_uint(x); }
__device__ __forceinline__ uint32_t smem_u32(const void* p) {
    uint32_t a;
    asm("{ .reg .u64 t; cvta.to.shared.u64 t, %1; cvt.u32.u64 %0, t; }"
        : "=r"(a) : "l"(p));
    return a;
}
__device__ __forceinline__ void cpa16(uint32_t s, const void* g) {
    asm volatile("cp.async.ca.shared.global [%0], [%1], 16;" :: "r"(s), "l"(g));
}
#define CP_COMMIT() asm volatile("cp.async.commit_group;" ::: "memory")
#define CP_WAIT1()  asm volatile("cp.async.wait_group 1;" ::: "memory")

// D += A(16x8, row) * B(8x8, col), tf32 inputs, fp32 accum
__device__ __forceinline__ void mma8(float d[4], uint32_t a0, uint32_t a1,
                                     uint32_t a2, uint32_t a3,
                                     uint32_t b0, uint32_t b1) {
    asm volatile(
        "mma.sync.aligned.m16n8k8.row.col.f32.tf32.tf32.f32 "
        "{%0,%1,%2,%3}, {%4,%5,%6,%7}, {%8,%9}, {%0,%1,%2,%3};"
        : "+f"(d[0]), "+f"(d[1]), "+f"(d[2]), "+f"(d[3])
        : "r"(a0), "r"(a1), "r"(a2), "r"(a3), "r"(b0), "r"(b1));
}

// ================= prep kernels ============================================
__global__ __launch_bounds__(256) void round_x(const float* __restrict__ x) {
    int i = blockIdx.x * 256 + threadIdx.x;      // float4 index
    float4 v = ((const float4*)x)[i];
    v.x = tf32r(v.x); v.y = tf32r(v.y); v.z = tf32r(v.z); v.w = tf32r(v.w);
    ((float4*)g_xr)[i] = v;
}

__global__ __launch_bounds__(256) void transpose4(
    const float* __restrict__ W0, const float* __restrict__ W1,
    const float* __restrict__ W2, const float* __restrict__ W3)
{
    __shared__ float t[32][33];
    const float* src = (blockIdx.z == 0) ? W0 : (blockIdx.z == 1) ? W1
                     : (blockIdx.z == 2) ? W2 : W3;
    float* dst = g_wt + (size_t)blockIdx.z * DM * DM;
    int bk = blockIdx.y * 32, bn = blockIdx.x * 32;
    int tx = threadIdx.x & 31, ty = threadIdx.x >> 5;
#pragma unroll
    for (int i = 0; i < 4; i++)
        t[ty + 8 * i][tx] = tf32r(src[(size_t)(bk + ty + 8 * i) * DM + bn + tx]);
    __syncthreads();
#pragma unroll
    for (int i = 0; i < 4; i++)
        dst[(size_t)(bn + ty + 8 * i) * DM + bk + tx] = t[tx][ty + 8 * i];
}

// ====== tf32 mma.sync GEMM with cp.async 2-stage pipeline ==================
// BM=BN=128, BK=32; 256 threads = 8 warps (2x4); warp tile 64x32.
// smem pitch 36 (conflict-free fragment loads). QKV mode fuses 3 weights.
#define GBM 128
#define GBN 128
#define GBK 32
#define TILE_F (128 * 36)                     // floats per (A or B) tile
#define GSMEM  (2 * 2 * TILE_F * 4)           // 73728 B

template<bool ROUND_OUT, bool HAS_BIAS, bool QKV>
__global__ __launch_bounds__(256, 2) void gemm_cp(
    const float* __restrict__ A, const float* __restrict__ BtBase,
    float* __restrict__ Cbase, const float* __restrict__ bias)
{
    extern __shared__ float gsm[];

    const int tid = threadIdx.x;
    const int warp = tid >> 5, lane = tid & 31;
    const int g = lane >> 2, t = lane & 3;
    const int wm = (warp >> 2) * 64;
    const int wn = (warp & 3) * 32;
    const int m0 = blockIdx.y * GBM;
    const int n_glob = blockIdx.x * GBN;

    const float* Bt = BtBase + (size_t)n_glob * DM;
    float* C;
    int c0;
    if (QKV) {
        int mat = n_glob >> 10;
        C = (mat == 0) ? g_q : (mat == 1) ? g_k : g_v;
        c0 = n_glob & 1023;
    } else {
        C = Cbase;
        c0 = n_glob;
    }

    const uint32_t sbase = smem_u32(gsm);
    // per-thread load slots (4 chunks A + 4 chunks B)
    int lrow[4], lc4[4];
#pragma unroll
    for (int it = 0; it < 4; it++) {
        int idx = tid + it * 256;
        lrow[it] = idx >> 3;
        lc4[it]  = (idx & 7) << 2;
    }

    // prologue: stage 0 (kt=0), stage 1 (kt=32)
#pragma unroll
    for (int st = 0; st < 2; st++) {
        int kt = st * GBK;
        uint32_t sa = sbase + (st * 2 * TILE_F) * 4;
        uint32_t sb = sa + TILE_F * 4;
#pragma unroll
        for (int it = 0; it < 4; it++) {
            cpa16(sa + (lrow[it] * 36 + lc4[it]) * 4,
                  &A[(size_t)(m0 + lrow[it]) * DM + kt + lc4[it]]);
            cpa16(sb + (lrow[it] * 36 + lc4[it]) * 4,
                  &Bt[(size_t)lrow[it] * DM + kt + lc4[it]]);
        }
        CP_COMMIT();
    }

    float acc[4][4][4] = {};

    const int NK = DM / GBK;   // 32
    for (int i = 0; i < NK; i++) {
        CP_WAIT1();
        __syncthreads();
        const int st = i & 1;
        const float* Ast = gsm + st * 2 * TILE_F;
        const float* Bst = Ast + TILE_F;

#pragma unroll
        for (int ks = 0; ks < 4; ks++) {
            const int k8 = ks * 8;
            uint32_t af[4][4];
#pragma unroll
            for (int mt = 0; mt < 4; mt++) {
                int ar = wm + mt * 16;
                af[mt][0] = fu(Ast[(ar + g) * 36 + k8 + t]);
                af[mt][1] = fu(Ast[(ar + g + 8) * 36 + k8 + t]);
                af[mt][2] = fu(Ast[(ar + g) * 36 + k8 + t + 4]);
                af[mt][3] = fu(Ast[(ar + g + 8) * 36 + k8 + t + 4]);
            }
#pragma unroll
            for (int nt = 0; nt < 4; nt++) {
                int bc = wn + nt * 8;
                uint32_t b0 = fu(Bst[(bc + g) * 36 + k8 + t]);
                uint32_t b1 = fu(Bst[(bc + g) * 36 + k8 + t + 4]);
#pragma unroll
                for (int mt = 0; mt < 4; mt++)
                    mma8(acc[mt][nt], af[mt][0], af[mt][1], af[mt][2], af[mt][3],
                         b0, b1);
            }
        }
        __syncthreads();

        if (i + 2 < NK) {
            int kt = (i + 2) * GBK;
            uint32_t sa = sbase + (st * 2 * TILE_F) * 4;
            uint32_t sb = sa + TILE_F * 4;
#pragma unroll
            for (int it = 0; it < 4; it++) {
                cpa16(sa + (lrow[it] * 36 + lc4[it]) * 4,
                      &A[(size_t)(m0 + lrow[it]) * DM + kt + lc4[it]]);
                cpa16(sb + (lrow[it] * 36 + lc4[it]) * 4,
                      &Bt[(size_t)lrow[it] * DM + kt + lc4[it]]);
            }
        }
        CP_COMMIT();
    }

#pragma unroll
    for (int mt = 0; mt < 4; mt++) {
        int r0 = m0 + wm + mt * 16 + g;
#pragma unroll
        for (int nt = 0; nt < 4; nt++) {
            int col = c0 + wn + nt * 8 + 2 * t;
            float v0 = acc[mt][nt][0], v1 = acc[mt][nt][1];
            float v2 = acc[mt][nt][2], v3 = acc[mt][nt][3];
            if (HAS_BIAS) {
                float bv0 = bias[col], bv1 = bias[col + 1];
                v0 += bv0; v1 += bv1; v2 += bv0; v3 += bv1;
            }
            if (ROUND_OUT) {
                v0 = tf32r(v0); v1 = tf32r(v1); v2 = tf32r(v2); v3 = tf32r(v3);
            }
            *(float2*)&C[(size_t)r0 * DM + col] = make_float2(v0, v1);
            *(float2*)&C[(size_t)(r0 + 8) * DM + col] = make_float2(v2, v3);
        }
    }
}

// ============== flash attention with tf32 mma.sync, causal =================
// Q/K/V pre-rounded to tf32 by the QKV GEMM epilogue; no cvt on load.
#define QP 68
#define VP 72
#define ASMEM ((64 * (QP + QP + VP + QP)) * sizeof(float))   // 70656 B

__global__ __launch_bounds__(128) void attn_mma()
{
    extern __shared__ float sm[];
    float* Qs = sm;
    float* Ks = Qs + 64 * QP;
    float* Vs = Ks + 64 * QP;
    float* Ps = Vs + 64 * VP;

    const int qt = blockIdx.x, h = blockIdx.y, b = blockIdx.z;
    const int tid = threadIdx.x;
    const int warp = tid >> 5, lane = tid & 31;
    const int g = lane >> 2, t = lane & 3;
    const int q0 = qt * 64;
    const int qrow = warp * 16;
    const size_t headoff = (size_t)b * SEQ * DM + (size_t)h * HD;

#pragma unroll
    for (int it = 0; it < 8; it++) {
        int idx = tid + it * 128;
        int row = idx >> 4, c = (idx & 15) << 2;
        *(float4*)&Qs[row * QP + c] =
            *(const float4*)&g_q[headoff + (size_t)(q0 + row) * DM + c];
    }

    float m0r = -1e30f, m1r = -1e30f, l0 = 0.f, l1 = 0.f;
    float oacc[8][4] = {};
    __syncthreads();

    for (int jt = 0; jt <= qt; jt++) {
        const int k0 = jt * 64;
#pragma unroll
        for (int it = 0; it < 8; it++) {
            int idx = tid + it * 128;
            int row = idx >> 4, c = (idx & 15) << 2;
            *(float4*)&Ks[row * QP + c] =
                *(const float4*)&g_k[headoff + (size_t)(k0 + row) * DM + c];
            *(float4*)&Vs[row * VP + c] =
                *(const float4*)&g_v[headoff + (size_t)(k0 + row) * DM + c];
        }
        __syncthreads();

        float sacc[8][4] = {};
#pragma unroll
        for (int ks = 0; ks < 8; ks++) {
            const int k8 = ks * 8;
            uint32_t a0 = fu(Qs[(qrow + g) * QP + k8 + t]);
            uint32_t a1 = fu(Qs[(qrow + g + 8) * QP + k8 + t]);
            uint32_t a2 = fu(Qs[(qrow + g) * QP + k8 + t + 4]);
            uint32_t a3 = fu(Qs[(qrow + g + 8) * QP + k8 + t + 4]);
#pragma unroll
            for (int nt = 0; nt < 8; nt++) {
                uint32_t b0 = fu(Ks[(nt * 8 + g) * QP + k8 + t]);
                uint32_t b1 = fu(Ks[(nt * 8 + g) * QP + k8 + t + 4]);
                mma8(sacc[nt], a0, a1, a2, a3, b0, b1);
            }
        }

        const int r0 = q0 + qrow + g, r1 = r0 + 8;
        if (jt == qt) {
#pragma unroll
            for (int nt = 0; nt < 8; nt++) {
                int c0 = k0 + nt * 8 + 2 * t, c1 = c0 + 1;
                if (c0 > r0) sacc[nt][0] = -1e9f;
                if (c1 > r0) sacc[nt][1] = -1e9f;
                if (c0 > r1) sacc[nt][2] = -1e9f;
                if (c1 > r1) sacc[nt][3] = -1e9f;
            }
        }
#pragma unroll
        for (int nt = 0; nt < 8; nt++)
#pragma unroll
            for (int j = 0; j < 4; j++) sacc[nt][j] *= 0.125f;

        float rm0 = -1e30f, rm1 = -1e30f;
#pragma unroll
        for (int nt = 0; nt < 8; nt++) {
            rm0 = fmaxf(rm0, fmaxf(sacc[nt][0], sacc[nt][1]));
            rm1 = fmaxf(rm1, fmaxf(sacc[nt][2], sacc[nt][3]));
        }
#pragma unroll
        for (int off = 1; off < 4; off <<= 1) {
            rm0 = fmaxf(rm0, __shfl_xor_sync(0xffffffffu, rm0, off));
            rm1 = fmaxf(rm1, __shfl_xor_sync(0xffffffffu, rm1, off));
        }
        float mn0 = fmaxf(m0r, rm0), mn1 = fmaxf(m1r, rm1);
        float al0 = __expf(m0r - mn0), al1 = __expf(m1r - mn1);
        float rs0 = 0.f, rs1 = 0.f;
#pragma unroll
        for (int nt = 0; nt < 8; nt++) {
            sacc[nt][0] = __expf(sacc[nt][0] - mn0);
            sacc[nt][1] = __expf(sacc[nt][1] - mn0);
            sacc[nt][2] = __expf(sacc[nt][2] - mn1);
            sacc[nt][3] = __expf(sacc[nt][3] - mn1);
            rs0 += sacc[nt][0] + sacc[nt][1];
            rs1 += sacc[nt][2] + sacc[nt][3];
        }
#pragma unroll
        for (int off = 1; off < 4; off <<= 1) {
            rs0 += __shfl_xor_sync(0xffffffffu, rs0, off);
            rs1 += __shfl_xor_sync(0xffffffffu, rs1, off);
        }
        l0 = l0 * al0 + rs0;
        l1 = l1 * al1 + rs1;
        m0r = mn0; m1r = mn1;
#pragma unroll
        for (int nt = 0; nt < 8; nt++) {
            oacc[nt][0] *= al0; oacc[nt][1] *= al0;
            oacc[nt][2] *= al1; oacc[nt][3] *= al1;
        }

#pragma unroll
        for (int nt = 0; nt < 8; nt++) {
            *(float2*)&Ps[(qrow + g) * QP + nt * 8 + 2 * t] =
                make_float2(tf32r(sacc[nt][0]), tf32r(sacc[nt][1]));
            *(float2*)&Ps[(qrow + g + 8) * QP + nt * 8 + 2 * t] =
                make_float2(tf32r(sacc[nt][2]), tf32r(sacc[nt][3]));
        }
        __syncwarp();

#pragma unroll
        for (int ks = 0; ks < 8; ks++) {
            const int k8 = ks * 8;
            uint32_t a0 = fu(Ps[(qrow + g) * QP + k8 + t]);
            uint32_t a1 = fu(Ps[(qrow + g + 8) * QP + k8 + t]);
            uint32_t a2 = fu(Ps[(qrow + g) * QP + k8 + t + 4]);
            uint32_t a3 = fu(Ps[(qrow + g + 8) * QP + k8 + t + 4]);
#pragma unroll
            for (int nt = 0; nt < 8; nt++) {
                uint32_t b0 = fu(Vs[(k8 + t) * VP + nt * 8 + g]);
                uint32_t b1 = fu(Vs[(k8 + t + 4) * VP + nt * 8 + g]);
                mma8(oacc[nt], a0, a1, a2, a3, b0, b1);
            }
        }
        __syncthreads();
    }

    const float inv0 = 1.f / l0, inv1 = 1.f / l1;
    const int r0 = q0 + qrow + g, r1 = r0 + 8;
#pragma unroll
    for (int nt = 0; nt < 8; nt++) {
        int c = nt * 8 + 2 * t;
        *(float2*)&g_ctx[headoff + (size_t)r0 * DM + c] =
            make_float2(tf32r(oacc[nt][0] * inv0), tf32r(oacc[nt][1] * inv0));
        *(float2*)&g_ctx[headoff + (size_t)r1 * DM + c] =
            make_float2(tf32r(oacc[nt][2] * inv1), tf32r(oacc[nt][3] * inv1));
    }
}

// ---------------- launch ---------------------------------------------------
extern "C" void kernel_launch(void* const* d_in, const int* in_sizes, int n_in,
                              void* d_out, int out_size)
{
    const float* x  = (const float*)d_in[0];
    const float* Wq = (const float*)d_in[1];
    const float* Wk = (const float*)d_in[2];
    const float* Wv = (const float*)d_in[3];
    const float* Wo = (const float*)d_in[4];
    const float* bo = (const float*)d_in[5];
    float* out = (float*)d_out;

    float *gxr, *gctx, *gwt;
    cudaGetSymbolAddress((void**)&gxr, g_xr);
    cudaGetSymbolAddress((void**)&gctx, g_ctx);
    cudaGetSymbolAddress((void**)&gwt, g_wt);

    round_x<<<MTOT * DM / 4 / 256, 256>>>(x);
    transpose4<<<dim3(32, 32, 4), 256>>>(Wq, Wk, Wv, Wo);

    cudaFuncSetAttribute(gemm_cp<true, false, true>,
                         cudaFuncAttributeMaxDynamicSharedMemorySize, GSMEM);
    cudaFuncSetAttribute(gemm_cp<false, true, false>,
                         cudaFuncAttributeMaxDynamicSharedMemorySize, GSMEM);

    // fused QKV: C columns span [0,3072)
    gemm_cp<true, false, true><<<dim3(3 * DM / GBN, MTOT / GBM), 256, GSMEM>>>(
        gxr, gwt, nullptr, nullptr);

    cudaFuncSetAttribute(attn_mma,
                         cudaFuncAttributeMaxDynamicSharedMemorySize, (int)ASMEM);
    attn_mma<<<dim3(SEQ / 64, NHEADS, BATCH), 128, ASMEM>>>();

    gemm_cp<false, true, false><<<dim3(DM / GBN, MTOT / GBM), 256, GSMEM>>>(
        gctx, gwt + 3 * (size_t)DM * DM, out, bo);
}

// round 6
// speedup vs baseline: 4.4182x; 1.0332x over previous
#include <cuda_runtime.h>
#include <math.h>
#include <stdint.h>

#define BATCH  2
#define SEQ    2048
#define DM     1024
#define NHEADS 16
#define HD     64
#define MTOT   (BATCH * SEQ)   // 4096

// ---------------- scratch (static device globals; no runtime alloc) --------
__device__ float g_q[MTOT * DM];
__device__ float g_k[MTOT * DM];
__device__ float g_v[MTOT * DM];
__device__ float g_ctx[MTOT * DM];
__device__ float g_xr[MTOT * DM];     // x rounded to tf32
__device__ float g_wt[4 * DM * DM];   // transposed tf32-rounded weights [N][K]

// ============================ helpers ======================================
__device__ __forceinline__ float tf32r(float x) {
    uint32_t r;
    asm("cvt.rna.tf32.f32 %0, %1;" : "=r"(r) : "f"(x));
    return __uint_as_float(r);
}
__device__ __forceinline__ uint32_t fu(float x) { return __float_as_uint(x); }
__device__ __forceinline__ uint32_t smem_u32(const void* p) {
    uint32_t a;
    asm("{ .reg .u64 t; cvta.to.shared.u64 t, %1; cvt.u32.u64 %0, t; }"
        : "=r"(a) : "l"(p));
    return a;
}
__device__ __forceinline__ void cpa16(uint32_t s, const void* g) {
    asm volatile("cp.async.ca.shared.global [%0], [%1], 16;" :: "r"(s), "l"(g));
}
#define CP_COMMIT() asm volatile("cp.async.commit_group;" ::: "memory")
#define CP_WAIT1()  asm volatile("cp.async.wait_group 1;" ::: "memory")

// D += A(16x8, row) * B(8x8, col), tf32 inputs, fp32 accum
__device__ __forceinline__ void mma8(float d[4], uint32_t a0, uint32_t a1,
                                     uint32_t a2, uint32_t a3,
                                     uint32_t b0, uint32_t b1) {
    asm volatile(
        "mma.sync.aligned.m16n8k8.row.col.f32.tf32.tf32.f32 "
        "{%0,%1,%2,%3}, {%4,%5,%6,%7}, {%8,%9}, {%0,%1,%2,%3};"
        : "+f"(d[0]), "+f"(d[1]), "+f"(d[2]), "+f"(d[3])
        : "r"(a0), "r"(a1), "r"(a2), "r"(a3), "r"(b0), "r"(b1));
}

// ================= prep kernels ============================================
__global__ __launch_bounds__(256) void round_x(const float* __restrict__ x) {
    int i = blockIdx.x * 256 + threadIdx.x;
    float4 v = ((const float4*)x)[i];
    v.x = tf32r(v.x); v.y = tf32r(v.y); v.z = tf32r(v.z); v.w = tf32r(v.w);
    ((float4*)g_xr)[i] = v;
}

__global__ __launch_bounds__(256) void transpose4(
    const float* __restrict__ W0, const float* __restrict__ W1,
    const float* __restrict__ W2, const float* __restrict__ W3)
{
    __shared__ float t[32][33];
    const float* src = (blockIdx.z == 0) ? W0 : (blockIdx.z == 1) ? W1
                     : (blockIdx.z == 2) ? W2 : W3;
    float* dst = g_wt + (size_t)blockIdx.z * DM * DM;
    int bk = blockIdx.y * 32, bn = blockIdx.x * 32;
    int tx = threadIdx.x & 31, ty = threadIdx.x >> 5;
#pragma unroll
    for (int i = 0; i < 4; i++)
        t[ty + 8 * i][tx] = tf32r(src[(size_t)(bk + ty + 8 * i) * DM + bn + tx]);
    __syncthreads();
#pragma unroll
    for (int i = 0; i < 4; i++)
        dst[(size_t)(bn + ty + 8 * i) * DM + bk + tx] = t[tx][ty + 8 * i];
}

// ====== tf32 mma.sync GEMM with cp.async 2-stage pipeline (unchanged) ======
#define GBM 128
#define GBN 128
#define GBK 32
#define TILE_F (128 * 36)
#define GSMEM  (2 * 2 * TILE_F * 4)

template<bool ROUND_OUT, bool HAS_BIAS, bool QKV>
__global__ __launch_bounds__(256, 2) void gemm_cp(
    const float* __restrict__ A, const float* __restrict__ BtBase,
    float* __restrict__ Cbase, const float* __restrict__ bias)
{
    extern __shared__ float gsm[];

    const int tid = threadIdx.x;
    const int warp = tid >> 5, lane = tid & 31;
    const int g = lane >> 2, t = lane & 3;
    const int wm = (warp >> 2) * 64;
    const int wn = (warp & 3) * 32;
    const int m0 = blockIdx.y * GBM;
    const int n_glob = blockIdx.x * GBN;

    const float* Bt = BtBase + (size_t)n_glob * DM;
    float* C;
    int c0;
    if (QKV) {
        int mat = n_glob >> 10;
        C = (mat == 0) ? g_q : (mat == 1) ? g_k : g_v;
        c0 = n_glob & 1023;
    } else {
        C = Cbase;
        c0 = n_glob;
    }

    const uint32_t sbase = smem_u32(gsm);
    int lrow[4], lc4[4];
#pragma unroll
    for (int it = 0; it < 4; it++) {
        int idx = tid + it * 256;
        lrow[it] = idx >> 3;
        lc4[it]  = (idx & 7) << 2;
    }

#pragma unroll
    for (int st = 0; st < 2; st++) {
        int kt = st * GBK;
        uint32_t sa = sbase + (st * 2 * TILE_F) * 4;
        uint32_t sb = sa + TILE_F * 4;
#pragma unroll
        for (int it = 0; it < 4; it++) {
            cpa16(sa + (lrow[it] * 36 + lc4[it]) * 4,
                  &A[(size_t)(m0 + lrow[it]) * DM + kt + lc4[it]]);
            cpa16(sb + (lrow[it] * 36 + lc4[it]) * 4,
                  &Bt[(size_t)lrow[it] * DM + kt + lc4[it]]);
        }
        CP_COMMIT();
    }

    float acc[4][4][4] = {};

    const int NK = DM / GBK;
    for (int i = 0; i < NK; i++) {
        CP_WAIT1();
        __syncthreads();
        const int st = i & 1;
        const float* Ast = gsm + st * 2 * TILE_F;
        const float* Bst = Ast + TILE_F;

#pragma unroll
        for (int ks = 0; ks < 4; ks++) {
            const int k8 = ks * 8;
            uint32_t af[4][4];
#pragma unroll
            for (int mt = 0; mt < 4; mt++) {
                int ar = wm + mt * 16;
                af[mt][0] = fu(Ast[(ar + g) * 36 + k8 + t]);
                af[mt][1] = fu(Ast[(ar + g + 8) * 36 + k8 + t]);
                af[mt][2] = fu(Ast[(ar + g) * 36 + k8 + t + 4]);
                af[mt][3] = fu(Ast[(ar + g + 8) * 36 + k8 + t + 4]);
            }
#pragma unroll
            for (int nt = 0; nt < 4; nt++) {
                int bc = wn + nt * 8;
                uint32_t b0 = fu(Bst[(bc + g) * 36 + k8 + t]);
                uint32_t b1 = fu(Bst[(bc + g) * 36 + k8 + t + 4]);
#pragma unroll
                for (int mt = 0; mt < 4; mt++)
                    mma8(acc[mt][nt], af[mt][0], af[mt][1], af[mt][2], af[mt][3],
                         b0, b1);
            }
        }
        __syncthreads();

        if (i + 2 < NK) {
            int kt = (i + 2) * GBK;
            uint32_t sa = sbase + (st * 2 * TILE_F) * 4;
            uint32_t sb = sa + TILE_F * 4;
#pragma unroll
            for (int it = 0; it < 4; it++) {
                cpa16(sa + (lrow[it] * 36 + lc4[it]) * 4,
                      &A[(size_t)(m0 + lrow[it]) * DM + kt + lc4[it]]);
                cpa16(sb + (lrow[it] * 36 + lc4[it]) * 4,
                      &Bt[(size_t)lrow[it] * DM + kt + lc4[it]]);
            }
        }
        CP_COMMIT();
    }

#pragma unroll
    for (int mt = 0; mt < 4; mt++) {
        int r0 = m0 + wm + mt * 16 + g;
#pragma unroll
        for (int nt = 0; nt < 4; nt++) {
            int col = c0 + wn + nt * 8 + 2 * t;
            float v0 = acc[mt][nt][0], v1 = acc[mt][nt][1];
            float v2 = acc[mt][nt][2], v3 = acc[mt][nt][3];
            if (HAS_BIAS) {
                float bv0 = bias[col], bv1 = bias[col + 1];
                v0 += bv0; v1 += bv1; v2 += bv0; v3 += bv1;
            }
            if (ROUND_OUT) {
                v0 = tf32r(v0); v1 = tf32r(v1); v2 = tf32r(v2); v3 = tf32r(v3);
            }
            *(float2*)&C[(size_t)r0 * DM + col] = make_float2(v0, v1);
            *(float2*)&C[(size_t)(r0 + 8) * DM + col] = make_float2(v2, v3);
        }
    }
}

// ============== flash attention v2: Q-frags in regs, cp.async K/V ==========
// 64 queries/block, 4 warps. K/V double-buffered. Heavy qt blocks first.
#define KP 68
#define VP 72
#define PP 68
#define KV_F (64 * KP + 64 * VP)                       // one K+V stage
#define ASMEM ((2 * KV_F + 64 * PP) * sizeof(float))   // 89088 B

__global__ __launch_bounds__(128) void attn_mma()
{
    extern __shared__ float sm[];
    float* Ksb = sm;                    // [2][64][KP]
    float* Vsb = sm + 2 * 64 * KP;      // [2][64][VP]
    float* Ps  = sm + 2 * (64 * KP + 64 * VP);

    const int qt = gridDim.x - 1 - blockIdx.x;   // heavy blocks first
    const int h = blockIdx.y, b = blockIdx.z;
    const int tid = threadIdx.x;
    const int warp = tid >> 5, lane = tid & 31;
    const int g = lane >> 2, t = lane & 3;
    const int q0 = qt * 64;
    const int qrow = warp * 16;
    const size_t headoff = (size_t)b * SEQ * DM + (size_t)h * HD;

    const uint32_t skb = smem_u32(Ksb);
    const uint32_t svb = smem_u32(Vsb);
    const float* kgl = g_k + headoff;
    const float* vgl = g_v + headoff;

    // prefetch K/V tile 0 into buffer 0
    {
#pragma unroll
        for (int it = 0; it < 8; it++) {
            int idx = tid + it * 128;
            int row = idx >> 4, c4 = (idx & 15) << 2;
            cpa16(skb + (row * KP + c4) * 4, &kgl[(size_t)row * DM + c4]);
            cpa16(svb + (row * VP + c4) * 4, &vgl[(size_t)row * DM + c4]);
        }
        CP_COMMIT();
    }

    // hoist Q fragments (loop-invariant): straight from gmem
    uint32_t qf[8][4];
    {
        const float* qbase = g_q + headoff + (size_t)(q0 + qrow + g) * DM;
#pragma unroll
        for (int ks = 0; ks < 8; ks++) {
            int k8 = ks * 8;
            qf[ks][0] = fu(qbase[k8 + t]);
            qf[ks][1] = fu(qbase[8 * (size_t)DM + k8 + t]);
            qf[ks][2] = fu(qbase[k8 + t + 4]);
            qf[ks][3] = fu(qbase[8 * (size_t)DM + k8 + t + 4]);
        }
    }

    float m0r = -1e30f, m1r = -1e30f, l0 = 0.f, l1 = 0.f;
    float oacc[8][4] = {};

    for (int jt = 0; jt <= qt; jt++) {
        // prefetch next tile into the other buffer (or commit empty group)
        if (jt < qt) {
            const int nk0 = (jt + 1) * 64;
            const int nb = (jt + 1) & 1;
            uint32_t ka = skb + nb * 64 * KP * 4;
            uint32_t va = svb + nb * 64 * VP * 4;
#pragma unroll
            for (int it = 0; it < 8; it++) {
                int idx = tid + it * 128;
                int row = idx >> 4, c4 = (idx & 15) << 2;
                cpa16(ka + (row * KP + c4) * 4,
                      &kgl[(size_t)(nk0 + row) * DM + c4]);
                cpa16(va + (row * VP + c4) * 4,
                      &vgl[(size_t)(nk0 + row) * DM + c4]);
            }
        }
        CP_COMMIT();
        CP_WAIT1();
        __syncthreads();

        const float* Ks = Ksb + (jt & 1) * 64 * KP;
        const float* Vs = Vsb + (jt & 1) * 64 * VP;
        const int k0 = jt * 64;

        // S = Q @ K^T (warp: 16 x 64), Q frags from registers
        float sacc[8][4] = {};
#pragma unroll
        for (int ks = 0; ks < 8; ks++) {
            const int k8 = ks * 8;
#pragma unroll
            for (int nt = 0; nt < 8; nt++) {
                uint32_t b0 = fu(Ks[(nt * 8 + g) * KP + k8 + t]);
                uint32_t b1 = fu(Ks[(nt * 8 + g) * KP + k8 + t + 4]);
                mma8(sacc[nt], qf[ks][0], qf[ks][1], qf[ks][2], qf[ks][3],
                     b0, b1);
            }
        }

        const int r0 = q0 + qrow + g, r1 = r0 + 8;
        if (jt == qt) {
#pragma unroll
            for (int nt = 0; nt < 8; nt++) {
                int c0 = k0 + nt * 8 + 2 * t, c1 = c0 + 1;
                if (c0 > r0) sacc[nt][0] = -1e9f;
                if (c1 > r0) sacc[nt][1] = -1e9f;
                if (c0 > r1) sacc[nt][2] = -1e9f;
                if (c1 > r1) sacc[nt][3] = -1e9f;
            }
        }
#pragma unroll
        for (int nt = 0; nt < 8; nt++)
#pragma unroll
            for (int j = 0; j < 4; j++) sacc[nt][j] *= 0.125f;

        // online softmax
        float rm0 = -1e30f, rm1 = -1e30f;
#pragma unroll
        for (int nt = 0; nt < 8; nt++) {
            rm0 = fmaxf(rm0, fmaxf(sacc[nt][0], sacc[nt][1]));
            rm1 = fmaxf(rm1, fmaxf(sacc[nt][2], sacc[nt][3]));
        }
#pragma unroll
        for (int off = 1; off < 4; off <<= 1) {
            rm0 = fmaxf(rm0, __shfl_xor_sync(0xffffffffu, rm0, off));
            rm1 = fmaxf(rm1, __shfl_xor_sync(0xffffffffu, rm1, off));
        }
        float mn0 = fmaxf(m0r, rm0), mn1 = fmaxf(m1r, rm1);
        float al0 = __expf(m0r - mn0), al1 = __expf(m1r - mn1);
        float rs0 = 0.f, rs1 = 0.f;
#pragma unroll
        for (int nt = 0; nt < 8; nt++) {
            sacc[nt][0] = __expf(sacc[nt][0] - mn0);
            sacc[nt][1] = __expf(sacc[nt][1] - mn0);
            sacc[nt][2] = __expf(sacc[nt][2] - mn1);
            sacc[nt][3] = __expf(sacc[nt][3] - mn1);
            rs0 += sacc[nt][0] + sacc[nt][1];
            rs1 += sacc[nt][2] + sacc[nt][3];
        }
#pragma unroll
        for (int off = 1; off < 4; off <<= 1) {
            rs0 += __shfl_xor_sync(0xffffffffu, rs0, off);
            rs1 += __shfl_xor_sync(0xffffffffu, rs1, off);
        }
        l0 = l0 * al0 + rs0;
        l1 = l1 * al1 + rs1;
        m0r = mn0; m1r = mn1;
#pragma unroll
        for (int nt = 0; nt < 8; nt++) {
            oacc[nt][0] *= al0; oacc[nt][1] *= al0;
            oacc[nt][2] *= al1; oacc[nt][3] *= al1;
        }

        // P -> smem (warp-private rows), reload as A-fragments
#pragma unroll
        for (int nt = 0; nt < 8; nt++) {
            *(float2*)&Ps[(qrow + g) * PP + nt * 8 + 2 * t] =
                make_float2(tf32r(sacc[nt][0]), tf32r(sacc[nt][1]));
            *(float2*)&Ps[(qrow + g + 8) * PP + nt * 8 + 2 * t] =
                make_float2(tf32r(sacc[nt][2]), tf32r(sacc[nt][3]));
        }
        __syncwarp();

        // O += P @ V
#pragma unroll
        for (int ks = 0; ks < 8; ks++) {
            const int k8 = ks * 8;
            uint32_t a0 = fu(Ps[(qrow + g) * PP + k8 + t]);
            uint32_t a1 = fu(Ps[(qrow + g + 8) * PP + k8 + t]);
            uint32_t a2 = fu(Ps[(qrow + g) * PP + k8 + t + 4]);
            uint32_t a3 = fu(Ps[(qrow + g + 8) * PP + k8 + t + 4]);
#pragma unroll
            for (int nt = 0; nt < 8; nt++) {
                uint32_t b0 = fu(Vs[(k8 + t) * VP + nt * 8 + g]);
                uint32_t b1 = fu(Vs[(k8 + t + 4) * VP + nt * 8 + g]);
                mma8(oacc[nt], a0, a1, a2, a3, b0, b1);
            }
        }
        __syncthreads();
    }

    const float inv0 = 1.f / l0, inv1 = 1.f / l1;
    const int r0 = q0 + qrow + g, r1 = r0 + 8;
#pragma unroll
    for (int nt = 0; nt < 8; nt++) {
        int c = nt * 8 + 2 * t;
        *(float2*)&g_ctx[headoff + (size_t)r0 * DM + c] =
            make_float2(tf32r(oacc[nt][0] * inv0), tf32r(oacc[nt][1] * inv0));
        *(float2*)&g_ctx[headoff + (size_t)r1 * DM + c] =
            make_float2(tf32r(oacc[nt][2] * inv1), tf32r(oacc[nt][3] * inv1));
    }
}

// ---------------- launch ---------------------------------------------------
extern "C" void kernel_launch(void* const* d_in, const int* in_sizes, int n_in,
                              void* d_out, int out_size)
{
    const float* x  = (const float*)d_in[0];
    const float* Wq = (const float*)d_in[1];
    const float* Wk = (const float*)d_in[2];
    const float* Wv = (const float*)d_in[3];
    const float* Wo = (const float*)d_in[4];
    const float* bo = (const float*)d_in[5];
    float* out = (float*)d_out;

    float *gxr, *gctx, *gwt;
    cudaGetSymbolAddress((void**)&gxr, g_xr);
    cudaGetSymbolAddress((void**)&gctx, g_ctx);
    cudaGetSymbolAddress((void**)&gwt, g_wt);

    round_x<<<MTOT * DM / 4 / 256, 256>>>(x);
    transpose4<<<dim3(32, 32, 4), 256>>>(Wq, Wk, Wv, Wo);

    cudaFuncSetAttribute(gemm_cp<true, false, true>,
                         cudaFuncAttributeMaxDynamicSharedMemorySize, GSMEM);
    cudaFuncSetAttribute(gemm_cp<false, true, false>,
                         cudaFuncAttributeMaxDynamicSharedMemorySize, GSMEM);

    gemm_cp<true, false, true><<<dim3(3 * DM / GBN, MTOT / GBM), 256, GSMEM>>>(
        gxr, gwt, nullptr, nullptr);

    cudaFuncSetAttribute(attn_mma,
                         cudaFuncAttributeMaxDynamicSharedMemorySize, (int)ASMEM);
    attn_mma<<<dim3(SEQ / 64, NHEADS, BATCH), 128, ASMEM>>>();

    gemm_cp<false, true, false><<<dim3(DM / GBN, MTOT / GBM), 256, GSMEM>>>(
        gctx, gwt + 3 * (size_t)DM * DM, out, bo);
}